// round 6
// baseline (speedup 1.0000x reference)
#include <cuda_runtime.h>

// Problem shape (fixed by the dataset): N=8, T=256, U=128, C=512
#define NN 8
#define TT 256
#define UU 128
#define U1 129
#define CC 512
#define SMAX 384      // T + U diagonals
#define UP 132        // padded u-stride for diagonal-major scratch
#define NEGF (-1e30f)

// Scratch (static __device__ globals — no allocation in kernel_launch)
__device__ float g_Bd[NN * SMAX * UP];   // blank[t][u] stored at [n][(t+u)][u]
__device__ float g_Ed[NN * SMAX * UP];   // emit[t][u]  stored at [n][(t+u)][u]
__device__ float g_loss[NN];

// ---------------------------------------------------------------------------
// Kernel 1: per-row log-sum-exp; emit only the blank/emit log-probs needed by
// the recursion, written in diagonal-major layout. One warp per (n,t,u) row.
// ---------------------------------------------------------------------------
__global__ __launch_bounds__(256) void lse_kernel(const float* __restrict__ acts,
                                                  const int* __restrict__ targets) {
    const int gw   = (blockIdx.x * blockDim.x + threadIdx.x) >> 5;
    const int lane = threadIdx.x & 31;
    const int NROWS = NN * TT * U1;
    if (gw >= NROWS) return;

    const int n = gw / (TT * U1);
    const int r = gw - n * (TT * U1);
    const int t = r / U1;
    const int u = r - t * U1;

    const float* x = acts + (size_t)gw * CC;

    // Prefetch target class early (lane 0 only needs it)
    int tgt = 0;
    if (lane == 0 && u < UU) tgt = __ldg(&targets[n * UU + u]);

    // 16 elements per lane, perfectly coalesced float4 loads
    float4 v0 = *(const float4*)(x + 4 * lane);
    float4 v1 = *(const float4*)(x + 4 * lane + 128);
    float4 v2 = *(const float4*)(x + 4 * lane + 256);
    float4 v3 = *(const float4*)(x + 4 * lane + 384);

    float m = fmaxf(fmaxf(fmaxf(v0.x, v0.y), fmaxf(v0.z, v0.w)),
                    fmaxf(fmaxf(v1.x, v1.y), fmaxf(v1.z, v1.w)));
    m = fmaxf(m, fmaxf(fmaxf(fmaxf(v2.x, v2.y), fmaxf(v2.z, v2.w)),
                       fmaxf(fmaxf(v3.x, v3.y), fmaxf(v3.z, v3.w))));
#pragma unroll
    for (int o = 16; o; o >>= 1)
        m = fmaxf(m, __shfl_xor_sync(0xffffffffu, m, o));

    float s = __expf(v0.x - m) + __expf(v0.y - m) + __expf(v0.z - m) + __expf(v0.w - m)
            + __expf(v1.x - m) + __expf(v1.y - m) + __expf(v1.z - m) + __expf(v1.w - m)
            + __expf(v2.x - m) + __expf(v2.y - m) + __expf(v2.z - m) + __expf(v2.w - m)
            + __expf(v3.x - m) + __expf(v3.y - m) + __expf(v3.z - m) + __expf(v3.w - m);
#pragma unroll
    for (int o = 16; o; o >>= 1)
        s += __shfl_xor_sync(0xffffffffu, s, o);

    const float lse = m + __logf(s);

    if (lane == 0) {
        const int sidx = (n * SMAX + (t + u)) * UP + u;
        g_Bd[sidx] = v0.x - lse;                      // x[0] is lane 0's v0.x
        if (u < UU) g_Ed[sidx] = __ldg(&x[tgt]) - lse; // L1 hit (row just loaded)
    }
}

// ---------------------------------------------------------------------------
// Kernel 2: anti-diagonal wavefront alpha recursion. One CTA per sample.
// Ping-pong shared row, 1 syncthreads/step, depth-4 register prefetch.
// ---------------------------------------------------------------------------
__global__ __launch_bounds__(160) void alpha_kernel(const int* __restrict__ alen,
                                                    const int* __restrict__ tlen) {
    const int n = blockIdx.x;
    const int u = threadIdx.x;                 // 0..159 (active compute: u <= UU)
    __shared__ float sA[2][UP];

    const float* Bd = g_Bd + n * SMAX * UP;
    const float* Ed = g_Ed + n * SMAX * UP;
    const int Tn = __ldg(&alen[n]);
    const int Un = __ldg(&tlen[n]);
    const int dloss = Tn - 1 + Un;

    if (u < UP) {
        sA[0][u] = (u == 0) ? 0.0f : NEGF;     // alpha[0][0] = 0 on diagonal 0
        sA[1][u] = NEGF;
    }
    __syncthreads();

    int p = 0;
    const bool act = (u <= UU);

    // Loads are predicated by exact entry-existence conditions, so no OOB reads
    // even for the pipeline's over-reaching prefetch indices.
#define LOADB(dn_) ((act && ((dn_) - u) >= 1 && ((dn_) - u) <= TT) \
                        ? __ldg(&Bd[((dn_) - 1) * UP + u]) : NEGF)
#define LOADE(dn_) ((act && u >= 1 && ((dn_) - u) >= 0 && ((dn_) - u) <= (TT - 1)) \
                        ? __ldg(&Ed[((dn_) - 1) * UP + (u - 1)]) : NEGF)

    float bv0 = LOADB(1), ev0 = LOADE(1);
    float bv1 = LOADB(2), ev1 = LOADE(2);
    float bv2 = LOADB(3), ev2 = LOADE(3);
    float bv3 = LOADB(4), ev3 = LOADE(4);

#define STEP(dn_, bv_, ev_) {                                                  \
        if (act) {                                                             \
            float au   = sA[p][u];                                             \
            float aum1 = (u > 0) ? sA[p][u - 1] : NEGF;                        \
            float b1 = au + (bv_);                                             \
            float b2 = aum1 + (ev_);                                           \
            float mx = fmaxf(b1, b2), mn = fminf(b1, b2);                      \
            float val = mx + __logf(1.0f + __expf(mn - mx));                   \
            sA[p ^ 1][u] = val;                                                \
            if ((dn_) == dloss && u == Un) {                                   \
                float bl = __ldg(&Bd[(dn_) * UP + u]); /* blank[Tn-1][Un] */   \
                g_loss[n] = -(val + bl);                                       \
            }                                                                  \
        }                                                                      \
        __syncthreads();                                                       \
        p ^= 1;                                                                \
    }

    for (int dn = 1; dn <= SMAX; dn += 4) {
        STEP(dn,     bv0, ev0); bv0 = LOADB(dn + 4); ev0 = LOADE(dn + 4);
        STEP(dn + 1, bv1, ev1); bv1 = LOADB(dn + 5); ev1 = LOADE(dn + 5);
        STEP(dn + 2, bv2, ev2); bv2 = LOADB(dn + 6); ev2 = LOADE(dn + 6);
        STEP(dn + 3, bv3, ev3); bv3 = LOADB(dn + 7); ev3 = LOADE(dn + 7);
    }
#undef STEP
#undef LOADB
#undef LOADE
}

// ---------------------------------------------------------------------------
// Kernel 3: mean over the 8 per-sample losses.
// ---------------------------------------------------------------------------
__global__ void finalize_kernel(float* __restrict__ out) {
    float s = (threadIdx.x < NN) ? g_loss[threadIdx.x] : 0.0f;
#pragma unroll
    for (int o = 16; o; o >>= 1)
        s += __shfl_xor_sync(0xffffffffu, s, o);
    if (threadIdx.x == 0) out[0] = s * (1.0f / NN);
}

extern "C" void kernel_launch(void* const* d_in, const int* in_sizes, int n_in,
                              void* d_out, int out_size) {
    const float* acts    = (const float*)d_in[0];
    const int*   targets = (const int*)d_in[1];
    const int*   alen    = (const int*)d_in[2];
    const int*   tlen    = (const int*)d_in[3];

    const int rows   = NN * TT * U1;            // 264,192 rows
    const int blocks = (rows * 32 + 255) / 256; // 1 warp per row, 8 warps/CTA

    lse_kernel<<<blocks, 256>>>(acts, targets);
    alpha_kernel<<<NN, 160>>>(alen, tlen);
    finalize_kernel<<<1, 32>>>((float*)d_out);
}

// round 7
// speedup vs baseline: 1.7638x; 1.7638x over previous
#include <cuda_runtime.h>

// Problem shape (fixed by the dataset): N=8, T=256, U=128, C=512
#define NN 8
#define TT 256
#define UU 128
#define U1 129
#define CC 512
#define SMAX 384        // T + U diagonals actually computed
#define SMAXP 390       // padded diagonal count (prefetch over-reach up to dn+7)
#define UPX 160         // padded u-stride (loads reach u = 32*4+31 = 159)
#define NEGF (-1e30f)
#define FULLMASK 0xffffffffu

// Scratch, diagonal-major: value for (t,u) lives at [(t+u)*UPX + u].
// +32 front guard absorbs the emit load at index -1 (u=0, k=0, dn=1).
#define ESZ (NN * SMAXP * UPX)
__device__ float g_Bd_raw[32 + ESZ];
__device__ float g_Ed_raw[32 + ESZ];
__device__ float g_loss[NN];

// ---------------------------------------------------------------------------
// Kernel 0: fill scratch (incl. guards/padding) with the -1e30 sentinel so the
// alpha kernel needs zero per-step boundary predicates.
// ---------------------------------------------------------------------------
__global__ void fill_kernel() {
    const int i = blockIdx.x * blockDim.x + threadIdx.x;
    const int total = (32 + ESZ) / 4;
    if (i < total) {
        float4 v = make_float4(NEGF, NEGF, NEGF, NEGF);
        ((float4*)g_Bd_raw)[i] = v;
        ((float4*)g_Ed_raw)[i] = v;
    }
}

// ---------------------------------------------------------------------------
// Kernel 1: per-row log-sum-exp; emit only blank/emit log-probs, written
// diagonal-major. One warp per (n,t,u) row. (85% DRAM — at roofline.)
// ---------------------------------------------------------------------------
__global__ __launch_bounds__(256) void lse_kernel(const float* __restrict__ acts,
                                                  const int* __restrict__ targets) {
    const int gw   = (blockIdx.x * blockDim.x + threadIdx.x) >> 5;
    const int lane = threadIdx.x & 31;
    const int NROWS = NN * TT * U1;
    if (gw >= NROWS) return;

    const int n = gw / (TT * U1);
    const int r = gw - n * (TT * U1);
    const int t = r / U1;
    const int u = r - t * U1;

    const float* x = acts + (size_t)gw * CC;

    int tgt = 0;
    if (lane == 0 && u < UU) tgt = __ldg(&targets[n * UU + u]);

    float4 v0 = *(const float4*)(x + 4 * lane);
    float4 v1 = *(const float4*)(x + 4 * lane + 128);
    float4 v2 = *(const float4*)(x + 4 * lane + 256);
    float4 v3 = *(const float4*)(x + 4 * lane + 384);

    float m = fmaxf(fmaxf(fmaxf(v0.x, v0.y), fmaxf(v0.z, v0.w)),
                    fmaxf(fmaxf(v1.x, v1.y), fmaxf(v1.z, v1.w)));
    m = fmaxf(m, fmaxf(fmaxf(fmaxf(v2.x, v2.y), fmaxf(v2.z, v2.w)),
                       fmaxf(fmaxf(v3.x, v3.y), fmaxf(v3.z, v3.w))));
#pragma unroll
    for (int o = 16; o; o >>= 1)
        m = fmaxf(m, __shfl_xor_sync(FULLMASK, m, o));

    float s = __expf(v0.x - m) + __expf(v0.y - m) + __expf(v0.z - m) + __expf(v0.w - m)
            + __expf(v1.x - m) + __expf(v1.y - m) + __expf(v1.z - m) + __expf(v1.w - m)
            + __expf(v2.x - m) + __expf(v2.y - m) + __expf(v2.z - m) + __expf(v2.w - m)
            + __expf(v3.x - m) + __expf(v3.y - m) + __expf(v3.z - m) + __expf(v3.w - m);
#pragma unroll
    for (int o = 16; o; o >>= 1)
        s += __shfl_xor_sync(FULLMASK, s, o);

    const float lse = m + __logf(s);

    if (lane == 0) {
        const int sidx = 32 + (n * SMAXP + (t + u)) * UPX + u;
        g_Bd_raw[sidx] = v0.x - lse;
        if (u < UU) g_Ed_raw[sidx] = __ldg(&x[tgt]) - lse;
    }
}

// ---------------------------------------------------------------------------
// Kernel 2: single-warp-per-sample wavefront. Alpha lives in 5 registers/lane
// (u = 32k + lane); the u-1 neighbor is a rotate-by-1 shuffle. No barriers,
// no shared memory. Depth-4 register prefetch of blank/emit hides L2.
// ---------------------------------------------------------------------------
__device__ __forceinline__ float lae(float x, float y) {
    float mx = fmaxf(x, y), mn = fminf(x, y);
    return mx + __logf(1.0f + __expf(mn - mx));
}

struct Slot { float B[5]; float E[5]; };

__device__ __forceinline__ void load_slot(Slot& s, const float* __restrict__ Bd,
                                          const float* __restrict__ Ed, int dn, int l) {
    const float* pb = Bd + (dn - 1) * UPX + l;
    const float* pe = Ed + (dn - 1) * UPX + l - 1;
#pragma unroll
    for (int k = 0; k < 5; k++) {
        s.B[k] = __ldg(pb + 32 * k);
        s.E[k] = __ldg(pe + 32 * k);
    }
}

__device__ __forceinline__ void step(float a[5], const Slot& s, int l) {
    float b[5], m[5];
#pragma unroll
    for (int k = 0; k < 5; k++)
        b[k] = __shfl_sync(FULLMASK, a[k], (l + 31) & 31);  // lane l <- lane l-1 (wrap)
    m[0] = (l == 0) ? NEGF : b[0];
#pragma unroll
    for (int k = 1; k < 5; k++)
        m[k] = (l == 0) ? b[k - 1] : b[k];  // u-1 for u=32k is lane31's slice k-1
#pragma unroll
    for (int k = 0; k < 5; k++)
        a[k] = lae(a[k] + s.B[k], m[k] + s.E[k]);
}

__global__ __launch_bounds__(32) void alpha_warp_kernel(const int* __restrict__ alen,
                                                        const int* __restrict__ tlen) {
    const int n = blockIdx.x;
    const int l = threadIdx.x;
    const float* Bd = g_Bd_raw + 32 + n * SMAXP * UPX;
    const float* Ed = g_Ed_raw + 32 + n * SMAXP * UPX;

    const int Tn = __ldg(&alen[n]);
    const int Un = __ldg(&tlen[n]);
    const int dloss = Tn - 1 + Un;
    const int kl = Un >> 5;
    const int ll = Un & 31;
    const float bl_final = __ldg(&Bd[dloss * UPX + Un]);  // blank[Tn-1][Un]

    float a[5] = { (l == 0) ? 0.0f : NEGF, NEGF, NEGF, NEGF, NEGF };  // diagonal 0

    Slot s0, s1, s2, s3;
    load_slot(s0, Bd, Ed, 1, l);
    load_slot(s1, Bd, Ed, 2, l);
    load_slot(s2, Bd, Ed, 3, l);
    load_slot(s3, Bd, Ed, 4, l);

#define CHECK_LOSS(dn_) {                                              \
        if ((dn_) == dloss) {                                          \
            float val = a[0];                                          \
            if (kl == 1) val = a[1];                                   \
            if (kl == 2) val = a[2];                                   \
            if (kl == 3) val = a[3];                                   \
            if (kl == 4) val = a[4];                                   \
            if (l == ll) g_loss[n] = -(val + bl_final);                \
        }                                                              \
    }

    for (int dn = 1; dn <= SMAX; dn += 4) {
        step(a, s0, l); CHECK_LOSS(dn);     load_slot(s0, Bd, Ed, dn + 4, l);
        step(a, s1, l); CHECK_LOSS(dn + 1); load_slot(s1, Bd, Ed, dn + 5, l);
        step(a, s2, l); CHECK_LOSS(dn + 2); load_slot(s2, Bd, Ed, dn + 6, l);
        step(a, s3, l); CHECK_LOSS(dn + 3); load_slot(s3, Bd, Ed, dn + 7, l);
    }
#undef CHECK_LOSS
}

// ---------------------------------------------------------------------------
// Kernel 3: mean over the 8 per-sample losses.
// ---------------------------------------------------------------------------
__global__ void finalize_kernel(float* __restrict__ out) {
    float s = (threadIdx.x < NN) ? g_loss[threadIdx.x] : 0.0f;
#pragma unroll
    for (int o = 16; o; o >>= 1)
        s += __shfl_xor_sync(FULLMASK, s, o);
    if (threadIdx.x == 0) out[0] = s * (1.0f / NN);
}

extern "C" void kernel_launch(void* const* d_in, const int* in_sizes, int n_in,
                              void* d_out, int out_size) {
    const float* acts    = (const float*)d_in[0];
    const int*   targets = (const int*)d_in[1];
    const int*   alen    = (const int*)d_in[2];
    const int*   tlen    = (const int*)d_in[3];

    const int fill_blocks = ((32 + ESZ) / 4 + 255) / 256;
    fill_kernel<<<fill_blocks, 256>>>();

    const int rows   = NN * TT * U1;             // 264,192 rows
    const int blocks = (rows * 32 + 255) / 256;  // 1 warp per row
    lse_kernel<<<blocks, 256>>>(acts, targets);

    alpha_warp_kernel<<<NN, 32>>>(alen, tlen);
    finalize_kernel<<<1, 32>>>((float*)d_out);
}